// round 12
// baseline (speedup 1.0000x reference)
#include <cuda_runtime.h>
#include <cuda_fp16.h>
#include <cstdint>

#define N_NODES 100000
#define N_EDGES 1600000
#define CH      128

typedef unsigned long long ull;

// Scratch (static device globals — no allocation in kernel_launch)
__device__ __align__(16) __half g_h16[(size_t)N_NODES * CH];  // 25.6 MB fp16 h
__device__ int   g_deg[N_NODES];
__device__ int   g_row[N_NODES];     // CSR row start (by dst, real edges)
__device__ int   g_fill[N_NODES];    // fill cursors
__device__ int   g_csr[N_EDGES];     // src ids grouped by dst
__device__ float g_nrm[N_EDGES];     // per-edge norm, precomputed at fill
__device__ int   g_any_hi;           // statically 0; reset each replay
__device__ int   g_is64;

// --------------------------------------- sniff dtype + init degree (fused) --
__global__ void k_sniff_deg(const int* __restrict__ w) {
    int t = blockIdx.x * blockDim.x + threadIdx.x;      // 100096 threads
    if (t < N_NODES) g_deg[t] = 1;
    int i = (int)(((long long)t * 1599983LL) % 1600000LL);
    if (w[2 * i + 1] != 0) g_any_hi = 1;
}

__global__ void k_sniff_fin() {
    g_is64 = (g_any_hi == 0);
    g_any_hi = 0;
}

__device__ __forceinline__ void edge_params(int* stride, int* dbase) {
    int f = g_is64;
    *stride = f ? 2 : 1;
    *dbase  = f ? 2 * N_EDGES : N_EDGES;
}

// ---------------------------------------------------------------- degree ----
__global__ void k_deg_count(const int* __restrict__ ei) {
    int e = blockIdx.x * blockDim.x + threadIdx.x;
    if (e >= N_EDGES) return;
    int stride, dbase; edge_params(&stride, &dbase);
    atomicAdd(&g_deg[ei[dbase + stride * e]], 1);
}

// ------------------------------------------------- CSR row-start (scan) -----
__global__ void __launch_bounds__(1024) k_scan() {
    __shared__ int part[1024];
    const int t   = threadIdx.x;
    const int PER = (N_NODES + 1023) / 1024;           // 98
    int s0 = t * PER;
    int e0 = min(s0 + PER, N_NODES);

    int sum = 0;
    for (int i = s0; i < e0; i++) sum += g_deg[i] - 1;
    part[t] = sum;
    __syncthreads();
    for (int off = 1; off < 1024; off <<= 1) {
        int v = (t >= off) ? part[t - off] : 0;
        __syncthreads();
        part[t] += v;
        __syncthreads();
    }
    int excl = (t == 0) ? 0 : part[t - 1];
    for (int i = s0; i < e0; i++) {
        g_row[i]  = excl;
        g_fill[i] = 0;
        excl += g_deg[i] - 1;
    }
}

// -------------------------------------------------------------- CSR fill ----
// Also precomputes the per-edge norm (degrees are final here).
__global__ void k_fill(const int* __restrict__ ei) {
    int e = blockIdx.x * blockDim.x + threadIdx.x;
    if (e >= N_EDGES) return;
    int stride, dbase; edge_params(&stride, &dbase);
    int s = ei[stride * e];
    int d = ei[dbase + stride * e];
    int pos = atomicAdd(&g_fill[d], 1);
    int idx = g_row[d] + pos;
    g_csr[idx] = s;
    g_nrm[idx] = rsqrtf((float)g_deg[s] * (float)g_deg[d]);
}

// ------------------------------------------------------------------ GEMM ----
// (R10 exact — proven 109.5 us.) h = x W^T + b; fused epilogue:
// out = h/deg (exact fp32 self term), g_h16 = fp16(h).
__global__ void __launch_bounds__(128) k_gemm(const float* __restrict__ x,
                                              const float* __restrict__ W,
                                              const float* __restrict__ bias,
                                              float* __restrict__ out) {
    __shared__ float xs[32][CH];
    __shared__ float wt[32][CH];   // wt[kk][o] = W[o][kc+kk]

    const int t    = threadIdx.x;
    const int w    = t >> 5;
    const int lane = t & 31;

    const float4* xg = (const float4*)(x + (size_t)blockIdx.x * 32 * CH);
    #pragma unroll
    for (int i = 0; i < 8; i++) {
        int v = t + i * 128;
        ((float4*)&xs[0][0])[v] = xg[v];
    }

    float4 b4 = ((const float4*)bias)[lane];
    ull acc[8][2];
    #pragma unroll
    for (int r = 0; r < 8; r++) {
        asm("mov.b64 %0, {%1, %2};" : "=l"(acc[r][0])
            : "r"(__float_as_uint(b4.x)), "r"(__float_as_uint(b4.y)));
        asm("mov.b64 %0, {%1, %2};" : "=l"(acc[r][1])
            : "r"(__float_as_uint(b4.z)), "r"(__float_as_uint(b4.w)));
    }

    for (int kc = 0; kc < CH; kc += 32) {
        __syncthreads();
        #pragma unroll
        for (int i = 0; i < 8; i++) {
            float4 f = *(const float4*)(W + (size_t)t * CH + kc + i * 4);
            wt[i * 4 + 0][t] = f.x;
            wt[i * 4 + 1][t] = f.y;
            wt[i * 4 + 2][t] = f.z;
            wt[i * 4 + 3][t] = f.w;
        }
        __syncthreads();

        #pragma unroll
        for (int g = 0; g < 8; g++) {
            const int k0 = g * 4;
            ulonglong2 bq0 = *(const ulonglong2*)&wt[k0 + 0][lane * 4];
            ulonglong2 bq1 = *(const ulonglong2*)&wt[k0 + 1][lane * 4];
            ulonglong2 bq2 = *(const ulonglong2*)&wt[k0 + 2][lane * 4];
            ulonglong2 bq3 = *(const ulonglong2*)&wt[k0 + 3][lane * 4];
            #pragma unroll
            for (int r = 0; r < 8; r++) {
                float4 a = *(const float4*)&xs[w * 8 + r][kc + k0];
                ull a0, a1, a2, a3;
                asm("mov.b64 %0, {%1, %1};" : "=l"(a0) : "r"(__float_as_uint(a.x)));
                asm("mov.b64 %0, {%1, %1};" : "=l"(a1) : "r"(__float_as_uint(a.y)));
                asm("mov.b64 %0, {%1, %1};" : "=l"(a2) : "r"(__float_as_uint(a.z)));
                asm("mov.b64 %0, {%1, %1};" : "=l"(a3) : "r"(__float_as_uint(a.w)));
                asm("fma.rn.f32x2 %0, %1, %2, %0;" : "+l"(acc[r][0]) : "l"(a0), "l"(bq0.x));
                asm("fma.rn.f32x2 %0, %1, %2, %0;" : "+l"(acc[r][1]) : "l"(a0), "l"(bq0.y));
                asm("fma.rn.f32x2 %0, %1, %2, %0;" : "+l"(acc[r][0]) : "l"(a1), "l"(bq1.x));
                asm("fma.rn.f32x2 %0, %1, %2, %0;" : "+l"(acc[r][1]) : "l"(a1), "l"(bq1.y));
                asm("fma.rn.f32x2 %0, %1, %2, %0;" : "+l"(acc[r][0]) : "l"(a2), "l"(bq2.x));
                asm("fma.rn.f32x2 %0, %1, %2, %0;" : "+l"(acc[r][1]) : "l"(a2), "l"(bq2.y));
                asm("fma.rn.f32x2 %0, %1, %2, %0;" : "+l"(acc[r][0]) : "l"(a3), "l"(bq3.x));
                asm("fma.rn.f32x2 %0, %1, %2, %0;" : "+l"(acc[r][1]) : "l"(a3), "l"(bq3.y));
            }
        }
    }

    #pragma unroll
    for (int r = 0; r < 8; r++) {
        unsigned int r0, r1, r2, r3;
        asm("mov.b64 {%0, %1}, %2;" : "=r"(r0), "=r"(r1) : "l"(acc[r][0]));
        asm("mov.b64 {%0, %1}, %2;" : "=r"(r2), "=r"(r3) : "l"(acc[r][1]));
        float4 hv = make_float4(__uint_as_float(r0), __uint_as_float(r1),
                                __uint_as_float(r2), __uint_as_float(r3));
        size_t row = (size_t)blockIdx.x * 32 + w * 8 + r;

        __half2 p0 = __floats2half2_rn(hv.x, hv.y);
        __half2 p1 = __floats2half2_rn(hv.z, hv.w);
        uint2 pk;
        pk.x = *(unsigned int*)&p0;
        pk.y = *(unsigned int*)&p1;
        ((uint2*)g_h16)[row * 32 + lane] = pk;

        float invd = 1.0f / (float)g_deg[row];
        ((float4*)out)[row * 32 + lane] =
            make_float4(hv.x * invd, hv.y * invd, hv.z * invd, hv.w * invd);
    }
}

// ----------------------------------------------------- CSR gather-aggregate -
// One warp per node, 8 warps/block. (sid, nrm) staged to smem in 32-chunks
// (no shfl), then a 4-wide unrolled loop of INDEPENDENT gathers (MLP=4).
// out[node] += sum (self term already in out from GEMM epilogue).
__global__ void __launch_bounds__(256) k_agg(float* __restrict__ out) {
    __shared__ int   s_sid[8][32];
    __shared__ float s_nm[8][32];

    int wid  = threadIdx.x >> 5;
    int lane = threadIdx.x & 31;
    int node = (blockIdx.x << 3) + wid;
    if (node >= N_NODES) return;

    int m = g_deg[node] - 1;             // real in-edges
    if (m == 0) return;                  // out already = self term
    int start = g_row[node];

    float4 acc = make_float4(0.f, 0.f, 0.f, 0.f);

    for (int base = 0; base < m; base += 32) {
        int cnt = min(32, m - base);
        if (lane < cnt) {
            s_sid[wid][lane] = g_csr[start + base + lane];
            s_nm[wid][lane]  = g_nrm[start + base + lane];
        }
        __syncwarp();

        int j = 0;
        for (; j + 4 <= cnt; j += 4) {
            int   i0 = s_sid[wid][j],     i1 = s_sid[wid][j + 1];
            int   i2 = s_sid[wid][j + 2], i3 = s_sid[wid][j + 3];
            float n0 = s_nm[wid][j],      n1 = s_nm[wid][j + 1];
            float n2 = s_nm[wid][j + 2],  n3 = s_nm[wid][j + 3];
            uint2 p0 = ((const uint2*)g_h16)[(size_t)i0 * 32 + lane];
            uint2 p1 = ((const uint2*)g_h16)[(size_t)i1 * 32 + lane];
            uint2 p2 = ((const uint2*)g_h16)[(size_t)i2 * 32 + lane];
            uint2 p3 = ((const uint2*)g_h16)[(size_t)i3 * 32 + lane];
            float2 a0 = __half22float2(*(const __half2*)&p0.x);
            float2 b0 = __half22float2(*(const __half2*)&p0.y);
            float2 a1 = __half22float2(*(const __half2*)&p1.x);
            float2 b1 = __half22float2(*(const __half2*)&p1.y);
            float2 a2 = __half22float2(*(const __half2*)&p2.x);
            float2 b2 = __half22float2(*(const __half2*)&p2.y);
            float2 a3 = __half22float2(*(const __half2*)&p3.x);
            float2 b3 = __half22float2(*(const __half2*)&p3.y);
            acc.x += a0.x * n0; acc.y += a0.y * n0; acc.z += b0.x * n0; acc.w += b0.y * n0;
            acc.x += a1.x * n1; acc.y += a1.y * n1; acc.z += b1.x * n1; acc.w += b1.y * n1;
            acc.x += a2.x * n2; acc.y += a2.y * n2; acc.z += b2.x * n2; acc.w += b2.y * n2;
            acc.x += a3.x * n3; acc.y += a3.y * n3; acc.z += b3.x * n3; acc.w += b3.y * n3;
        }
        for (; j < cnt; j++) {
            int   i0 = s_sid[wid][j];
            float n0 = s_nm[wid][j];
            uint2 p0 = ((const uint2*)g_h16)[(size_t)i0 * 32 + lane];
            float2 a0 = __half22float2(*(const __half2*)&p0.x);
            float2 b0 = __half22float2(*(const __half2*)&p0.y);
            acc.x += a0.x * n0; acc.y += a0.y * n0;
            acc.z += b0.x * n0; acc.w += b0.y * n0;
        }
        __syncwarp();
    }

    float4* po = (float4*)out + (size_t)node * 32 + lane;
    float4 o = *po;
    o.x += acc.x; o.y += acc.y; o.z += acc.z; o.w += acc.w;
    *po = o;
}

// ------------------------------------------------------------------- glue ---
extern "C" void kernel_launch(void* const* d_in, const int* in_sizes, int n_in,
                              void* d_out, int out_size) {
    const float* x  = (const float*)d_in[0];
    const int*   ei = (const int*)d_in[1];     // int32 or int64 (sniffed)
    const float* W  = (const float*)d_in[2];
    const float* b  = (const float*)d_in[3];
    float* out = (float*)d_out;

    k_sniff_deg<<<(N_NODES + 255) / 256, 256>>>(ei);   // launch 0
    k_sniff_fin<<<1, 1>>>();                           // launch 1
    k_deg_count<<<(N_EDGES + 255) / 256, 256>>>(ei);   // launch 2
    k_gemm<<<N_NODES / 32, 128>>>(x, W, b, out);       // launch 3 (profiled)
    k_scan<<<1, 1024>>>();                             // launch 4
    k_fill<<<(N_EDGES + 255) / 256, 256>>>(ei);        // launch 5
    k_agg<<<(N_NODES + 7) / 8, 256>>>(out);            // launch 6
}

// round 13
// speedup vs baseline: 1.1266x; 1.1266x over previous
#include <cuda_runtime.h>
#include <cuda_fp16.h>
#include <cuda_bf16.h>
#include <mma.h>
#include <cstdint>

using namespace nvcuda;

#define N_NODES 100000
#define N_EDGES 1600000
#define CH      128

// Scratch (static device globals — no allocation in kernel_launch)
__device__ __align__(16) __half g_h16[(size_t)N_NODES * CH];  // 25.6 MB fp16 h
__device__ int g_deg[N_NODES];
__device__ int g_any_hi;   // statically 0; reset by k_sniff_fin each replay
__device__ int g_is64;     // 1 if edge_index is int64
// W bf16 split images, row-major [o][k] (same layout as W)
__device__ __align__(16) __nv_bfloat16 g_Whi[CH * CH];
__device__ __align__(16) __nv_bfloat16 g_Wlo[CH * CH];

// ------------------- sniff dtype + init degree + W bf16 split (fused) -------
__global__ void k_sniff_deg(const int* __restrict__ w, const float* __restrict__ W) {
    int t = blockIdx.x * blockDim.x + threadIdx.x;      // 100096 threads
    if (t < N_NODES) g_deg[t] = 1;
    int i = (int)(((long long)t * 1599983LL) % 1600000LL);
    if (w[2 * i + 1] != 0) g_any_hi = 1;
    if (t < CH * CH) {
        float wv = W[t];
        __nv_bfloat16 hi = __float2bfloat16(wv);
        g_Whi[t] = hi;
        g_Wlo[t] = __float2bfloat16(wv - __bfloat162float(hi));
    }
}

__global__ void k_sniff_fin() {
    g_is64 = (g_any_hi == 0);
    g_any_hi = 0;                       // reset for next graph replay
}

__device__ __forceinline__ void edge_params(int* stride, int* dbase) {
    int f = g_is64;
    *stride = f ? 2 : 1;
    *dbase  = f ? 2 * N_EDGES : N_EDGES;
}

// ---------------------------------------------------------------- degree ----
__global__ void k_deg_count(const int* __restrict__ ei) {
    int e = blockIdx.x * blockDim.x + threadIdx.x;
    if (e >= N_EDGES) return;
    int stride, dbase; edge_params(&stride, &dbase);
    atomicAdd(&g_deg[ei[dbase + stride * e]], 1);
}

// ------------------------------------------------- wmma bf16 split GEMM -----
// h[m][o] = b[o] + sum_k x[m][k] * W[o][k]
// 3-term bf16 split: xh*Wh + xl*Wh + xh*Wl (f32 accumulate), err ~2^-17.
// Block = 64 rows, 128 threads (4 warps). Warp w -> rows [16w,16w+16),
// 8 col-tiles of 16. x staged to smem as bf16 hi/lo (32 KB, reused as f32
// epilogue staging). W frags loaded from L1-resident global images.
// Fused epilogue: out = h/deg (fp32 self term), g_h16 = fp16(h).
__device__ __forceinline__ unsigned int pack_bf2(__nv_bfloat16 a, __nv_bfloat16 b) {
    return (unsigned int)__bfloat16_as_ushort(a)
         | ((unsigned int)__bfloat16_as_ushort(b) << 16);
}

__global__ void __launch_bounds__(128, 4) k_gemm(const float* __restrict__ x,
                                                 const float* __restrict__ bias,
                                                 float* __restrict__ out) {
    __shared__ __align__(16) char sbuf[32768];   // xs(hi|lo) then f32 acc staging
    __shared__ float sbias[CH];

    __nv_bfloat16* xh = (__nv_bfloat16*)sbuf;              // [64][128]
    __nv_bfloat16* xl = (__nv_bfloat16*)(sbuf + 16384);    // [64][128]
    float*         sa = (float*)sbuf;                      // [64][128] (after)

    const int t = threadIdx.x;
    const int w = t >> 5;
    const size_t row0 = (size_t)blockIdx.x * 64;

    sbias[t] = bias[t];   // blockDim==CH==128

    // Stage x -> bf16 hi/lo in smem (zeros for rows >= N)
    #pragma unroll
    for (int i = 0; i < 16; i++) {
        int v = t + i * 128;            // float4 index in [0,2048)
        int r = v >> 5, q = v & 31;
        float4 f = make_float4(0.f, 0.f, 0.f, 0.f);
        if (row0 + r < N_NODES) f = ((const float4*)x)[(row0 + r) * 32 + q];
        __nv_bfloat16 hx = __float2bfloat16(f.x), hy = __float2bfloat16(f.y);
        __nv_bfloat16 hz = __float2bfloat16(f.z), hw = __float2bfloat16(f.w);
        uint2 ph, pl;
        ph.x = pack_bf2(hx, hy);
        ph.y = pack_bf2(hz, hw);
        pl.x = pack_bf2(__float2bfloat16(f.x - __bfloat162float(hx)),
                        __float2bfloat16(f.y - __bfloat162float(hy)));
        pl.y = pack_bf2(__float2bfloat16(f.z - __bfloat162float(hz)),
                        __float2bfloat16(f.w - __bfloat162float(hw)));
        ((uint2*)xh)[v] = ph;
        ((uint2*)xl)[v] = pl;
    }
    __syncthreads();

    wmma::fragment<wmma::accumulator, 16, 16, 16, float> acc[8];
    #pragma unroll
    for (int c = 0; c < 8; c++) wmma::fill_fragment(acc[c], 0.0f);

    wmma::fragment<wmma::matrix_a, 16, 16, 16, __nv_bfloat16, wmma::row_major> ah, al;
    wmma::fragment<wmma::matrix_b, 16, 16, 16, __nv_bfloat16, wmma::col_major> bh, bl;

    #pragma unroll
    for (int k0 = 0; k0 < CH; k0 += 16) {
        wmma::load_matrix_sync(ah, xh + (w * 16) * CH + k0, CH);
        wmma::load_matrix_sync(al, xl + (w * 16) * CH + k0, CH);
        #pragma unroll
        for (int c = 0; c < 8; c++) {
            wmma::load_matrix_sync(bh, g_Whi + (c * 16) * CH + k0, CH);
            wmma::load_matrix_sync(bl, g_Wlo + (c * 16) * CH + k0, CH);
            wmma::mma_sync(acc[c], ah, bh, acc[c]);
            wmma::mma_sync(acc[c], al, bh, acc[c]);
            wmma::mma_sync(acc[c], ah, bl, acc[c]);
        }
    }

    __syncthreads();   // xs no longer needed; reuse sbuf as f32 staging
    #pragma unroll
    for (int c = 0; c < 8; c++)
        wmma::store_matrix_sync(sa + (w * 16) * CH + c * 16, acc[c], CH,
                                wmma::mem_row_major);
    __syncthreads();

    // Epilogue: +bias; g_h16 = fp16(h); out = h/deg (exact fp32 self term)
    #pragma unroll
    for (int i = 0; i < 16; i++) {
        int v = t + i * 128;            // float4 index in [0,2048)
        int r = v >> 5, q = v & 31;
        size_t row = row0 + r;
        if (row < N_NODES) {
            float4 hv = ((const float4*)sa)[v];
            float4 bb = ((const float4*)sbias)[q];
            hv.x += bb.x; hv.y += bb.y; hv.z += bb.z; hv.w += bb.w;

            __half2 p0 = __floats2half2_rn(hv.x, hv.y);
            __half2 p1 = __floats2half2_rn(hv.z, hv.w);
            uint2 pk;
            pk.x = *(unsigned int*)&p0;
            pk.y = *(unsigned int*)&p1;
            ((uint2*)g_h16)[row * 32 + q] = pk;

            float invd = 1.0f / (float)g_deg[row];
            ((float4*)out)[row * 32 + q] =
                make_float4(hv.x * invd, hv.y * invd, hv.z * invd, hv.w * invd);
        }
    }
}

// ------------------------------------------------------------ edge scatter --
// One warp per edge: gather fp16 h[src], scale, vector red.add.v4 into out[dst].
__global__ void __launch_bounds__(256) k_edges(const int* __restrict__ ei,
                                               float* __restrict__ out) {
    int e    = (blockIdx.x << 3) + (threadIdx.x >> 5);
    int lane = threadIdx.x & 31;
    if (e >= N_EDGES) return;

    int stride, dbase; edge_params(&stride, &dbase);
    int s = ei[stride * e];
    int d = ei[dbase + stride * e];
    float nrm = rsqrtf((float)g_deg[s] * (float)g_deg[d]);

    uint2 pk = ((const uint2*)g_h16)[(size_t)s * 32 + lane];
    float2 f0 = __half22float2(*(const __half2*)&pk.x);
    float2 f1 = __half22float2(*(const __half2*)&pk.y);

    float* p = out + (size_t)d * CH + lane * 4;      // 16B aligned
    asm volatile("red.global.add.v4.f32 [%0], {%1, %2, %3, %4};"
                 :: "l"(p), "f"(f0.x * nrm), "f"(f0.y * nrm),
                    "f"(f1.x * nrm), "f"(f1.y * nrm)
                 : "memory");
}

// ------------------------------------------------------------------- glue ---
extern "C" void kernel_launch(void* const* d_in, const int* in_sizes, int n_in,
                              void* d_out, int out_size) {
    const float* x  = (const float*)d_in[0];
    const int*   ei = (const int*)d_in[1];     // int32 or int64 (sniffed)
    const float* W  = (const float*)d_in[2];
    const float* b  = (const float*)d_in[3];
    float* out = (float*)d_out;

    k_sniff_deg<<<(N_NODES + 255) / 256, 256>>>(ei, W);   // launch 0
    k_sniff_fin<<<1, 1>>>();                              // launch 1
    k_deg_count<<<(N_EDGES + 255) / 256, 256>>>(ei);      // launch 2
    k_gemm<<<(N_NODES + 63) / 64, 128>>>(x, b, out);      // launch 3 (profiled)
    k_edges<<<N_EDGES / 8, 256>>>(ei, out);               // launch 4
}